// round 1
// baseline (speedup 1.0000x reference)
#include <cuda_runtime.h>
#include <math.h>

#define LSP 13824            // 24*24*24
#define NB 2
#define C0 48
#define DI 96
#define NS 16
#define NCH 54               // scan chunks
#define CS 256               // chunk size (54*256 = 13824)

// ---------------- scratch (static device globals; no allocation) ----------------
__device__ float g_up[NB*C0*LSP];
__device__ float g_h1[NB*C0*LSP];
__device__ float g_h2[NB*C0*LSP];
__device__ float g_h3[NB*C0*LSP];
__device__ float g_Lx[NB*C0*LSP];
__device__ float g_mean[NB*C0];
__device__ float g_istd[NB*C0];
__device__ float g_xi[NB*DI*LSP];
__device__ float g_z [NB*DI*LSP];
__device__ float g_xs[NB*DI*LSP];
__device__ float g_delta[NB*DI*LSP];
__device__ float g_dx[NB*DI*LSP];
__device__ float g_Bm[NB*LSP*NS];
__device__ float g_Cm[NB*LSP*NS];
__device__ float g_P [NB*NCH*DI*NS];
__device__ float g_He[NB*NCH*DI*NS];
__device__ float g_ca[NB*NCH*DI*NS];
__device__ float g_y [NB*DI*LSP];

// ---------------- 1) trilinear 2x upsample, align_corners ----------------
__global__ void k_upsample(const float* __restrict__ x) {
    int idx = blockIdx.x * blockDim.x + threadIdx.x;
    if (idx >= NB*C0*LSP) return;
    int t = idx % 24; int r = idx / 24;
    int w = r % 24;  r /= 24;
    int h = r % 24;  r /= 24;          // r = b*48 + c
    const float sc = 11.0f / 23.0f;
    float ph = h * sc, pw = w * sc, pt = t * sc;
    int hl = (int)ph, wl = (int)pw, tl = (int)pt;
    float fh = ph - hl, fw = pw - wl, ft = pt - tl;
    int hh = min(hl + 1, 11), wh = min(wl + 1, 11), th = min(tl + 1, 11);
    const float* bp = x + r * 1728;
    float c000 = bp[hl*144 + wl*12 + tl];
    float c001 = bp[hl*144 + wl*12 + th];
    float c010 = bp[hl*144 + wh*12 + tl];
    float c011 = bp[hl*144 + wh*12 + th];
    float c100 = bp[hh*144 + wl*12 + tl];
    float c101 = bp[hh*144 + wl*12 + th];
    float c110 = bp[hh*144 + wh*12 + tl];
    float c111 = bp[hh*144 + wh*12 + th];
    float v00 = c000 + (c001 - c000) * ft;
    float v01 = c010 + (c011 - c010) * ft;
    float v10 = c100 + (c101 - c100) * ft;
    float v11 = c110 + (c111 - c110) * ft;
    float v0 = v00 + (v01 - v00) * fw;
    float v1 = v10 + (v11 - v10) * fw;
    g_up[idx] = v0 + (v1 - v0) * fh;
}

// ---------------- 2) 1x1 conv over concat([up(48), Hx(96)]) -> h1 ----------------
__global__ void __launch_bounds__(128) k_conv1(const float* __restrict__ Hx,
                                               const float* __restrict__ W1,
                                               const float* __restrict__ b1) {
    __shared__ float sW[144 * 48];            // [ci][co]
    for (int i = threadIdx.x; i < 144 * 48; i += blockDim.x) {
        int ci = i / 48, co = i % 48;
        sW[i] = W1[co * 144 + ci];
    }
    __syncthreads();
    int g = blockIdx.x * blockDim.x + threadIdx.x;    // over NB*LSP
    int l = g % LSP, b = g / LSP;
    float acc[48];
#pragma unroll
    for (int i = 0; i < 48; i++) acc[i] = __ldg(b1 + i);
    for (int ci = 0; ci < 144; ci++) {
        float v = (ci < 48) ? __ldg(g_up + (b*48 + ci)*LSP + l)
                            : __ldg(Hx + (b*96 + (ci - 48))*LSP + l);
        const float4* wp = (const float4*)(sW + ci * 48);
#pragma unroll
        for (int q = 0; q < 12; q++) {
            float4 w = wp[q];
            acc[4*q+0] += w.x * v; acc[4*q+1] += w.y * v;
            acc[4*q+2] += w.z * v; acc[4*q+3] += w.w * v;
        }
    }
#pragma unroll
    for (int co = 0; co < 48; co++)
        g_h1[(b*48 + co)*LSP + l] = acc[co];
}

// ---------------- 3) 3x3x3 conv, pad 1, 48->48 : h1 -> h2 ----------------
__global__ void __launch_bounds__(256) k_conv2(const float* __restrict__ W2,
                                               const float* __restrict__ b2) {
    __shared__ float sIn[8 * 600];            // 8 ci x (6z x 10y x 10x)
    __shared__ float sW[8 * 27 * 16];         // [ci][k][co]
    int bz = blockIdx.z;                      // b*3 + cog
    int b = bz / 3, cog = bz % 3;
    int zt = blockIdx.y;
    int yt = blockIdx.x / 3, xt = blockIdx.x % 3;
    int z0 = zt * 4, y0 = yt * 8, x0 = xt * 8;
    int tx = threadIdx.x, ty = threadIdx.y, tz = threadIdx.z;
    int tid = (tz * 8 + ty) * 8 + tx;
    float acc[16];
#pragma unroll
    for (int i = 0; i < 16; i++) acc[i] = 0.f;

    for (int cc = 0; cc < 6; cc++) {
        __syncthreads();
        for (int i = tid; i < 4800; i += 256) {
            int ci = i / 600; int p = i % 600;
            int lz = p / 100; int q = p % 100;
            int ly = q / 10;  int lx = q % 10;
            int gz = z0 - 1 + lz, gy = y0 - 1 + ly, gx = x0 - 1 + lx;
            float v = 0.f;
            if (gz >= 0 && gz < 24 && gy >= 0 && gy < 24 && gx >= 0 && gx < 24)
                v = g_h1[(b*48 + cc*8 + ci)*LSP + gz*576 + gy*24 + gx];
            sIn[i] = v;
        }
        for (int i = tid; i < 3456; i += 256) {
            int ci = i / (27 * 16); int k = (i / 16) % 27; int co = i % 16;
            sW[i] = W2[((cog*16 + co)*48 + cc*8 + ci)*27 + k];
        }
        __syncthreads();
#pragma unroll 1
        for (int ci = 0; ci < 8; ci++) {
            const float* ip = sIn + ci*600 + (tz*10 + ty)*10 + tx;
            const float* wp = sW + ci*27*16;
#pragma unroll
            for (int kz = 0; kz < 3; kz++)
#pragma unroll
            for (int ky = 0; ky < 3; ky++)
#pragma unroll
            for (int kx = 0; kx < 3; kx++) {
                float v = ip[kz*100 + ky*10 + kx];
                const float4* w4 = (const float4*)(wp + (kz*9 + ky*3 + kx)*16);
#pragma unroll
                for (int q = 0; q < 4; q++) {
                    float4 w = w4[q];
                    acc[4*q+0] += w.x * v; acc[4*q+1] += w.y * v;
                    acc[4*q+2] += w.z * v; acc[4*q+3] += w.w * v;
                }
            }
        }
    }
    int z = z0 + tz, y = y0 + ty, x = x0 + tx;
#pragma unroll
    for (int co = 0; co < 16; co++)
        g_h2[(b*48 + cog*16 + co)*LSP + z*576 + y*24 + x] = acc[co] + __ldg(b2 + cog*16 + co);
}

// ---------------- 4) 1x1 conv 48->48 : h2 -> h3 ----------------
__global__ void __launch_bounds__(128) k_conv3(const float* __restrict__ W3,
                                               const float* __restrict__ b3) {
    __shared__ float sW[48 * 48];
    for (int i = threadIdx.x; i < 48 * 48; i += blockDim.x) {
        int ci = i / 48, co = i % 48;
        sW[i] = W3[co * 48 + ci];
    }
    __syncthreads();
    int g = blockIdx.x * blockDim.x + threadIdx.x;
    int l = g % LSP, b = g / LSP;
    float acc[48];
#pragma unroll
    for (int i = 0; i < 48; i++) acc[i] = __ldg(b3 + i);
    for (int ci = 0; ci < 48; ci++) {
        float v = __ldg(g_h2 + (b*48 + ci)*LSP + l);
        const float4* wp = (const float4*)(sW + ci * 48);
#pragma unroll
        for (int q = 0; q < 12; q++) {
            float4 w = wp[q];
            acc[4*q+0] += w.x * v; acc[4*q+1] += w.y * v;
            acc[4*q+2] += w.z * v; acc[4*q+3] += w.w * v;
        }
    }
#pragma unroll
    for (int co = 0; co < 48; co++)
        g_h3[(b*48 + co)*LSP + l] = acc[co];
}

// ---------------- 5) instance-norm stats ----------------
__global__ void k_stats() {
    int bc = blockIdx.x;                      // 0..95
    const float* p = g_h3 + bc * LSP;
    float s1 = 0.f, s2 = 0.f;
    for (int i = threadIdx.x; i < LSP; i += blockDim.x) {
        float v = p[i]; s1 += v; s2 += v * v;
    }
    __shared__ float r1[256], r2[256];
    r1[threadIdx.x] = s1; r2[threadIdx.x] = s2; __syncthreads();
    for (int s = 128; s > 0; s >>= 1) {
        if (threadIdx.x < s) { r1[threadIdx.x] += r1[threadIdx.x + s];
                               r2[threadIdx.x] += r2[threadIdx.x + s]; }
        __syncthreads();
    }
    if (threadIdx.x == 0) {
        float m = r1[0] / (float)LSP;
        float var = r2[0] / (float)LSP - m * m;
        g_mean[bc] = m;
        g_istd[bc] = rsqrtf(var + 1e-5f);
    }
}

// ---------------- 6) normalize + SELU -> Lx ----------------
__global__ void k_selu() {
    int idx = blockIdx.x * blockDim.x + threadIdx.x;
    if (idx >= NB*C0*LSP) return;
    int bc = idx / LSP;
    float v = (g_h3[idx] - g_mean[bc]) * g_istd[bc];
    const float a = 1.6732632423543772f, s = 1.0507009873554805f;
    g_Lx[idx] = (v > 0.f) ? s * v : s * a * expm1f(v);
}

// ---------------- 7) in_proj 48 -> 192 (split xi / z) ----------------
__global__ void __launch_bounds__(128) k_inproj(const float* __restrict__ Wip) {
    __shared__ float sW[48 * 48];             // [ci][e_local]
    int eg = blockIdx.y, b = blockIdx.z;
    for (int i = threadIdx.x; i < 48 * 48; i += blockDim.x) {
        int ci = i / 48, el = i % 48;
        sW[i] = Wip[(eg*48 + el)*48 + ci];
    }
    __syncthreads();
    int l = blockIdx.x * blockDim.x + threadIdx.x;
    float acc[48];
#pragma unroll
    for (int i = 0; i < 48; i++) acc[i] = 0.f;
    for (int ci = 0; ci < 48; ci++) {
        float v = __ldg(g_Lx + (b*48 + ci)*LSP + l);
        const float4* wp = (const float4*)(sW + ci * 48);
#pragma unroll
        for (int q = 0; q < 12; q++) {
            float4 w = wp[q];
            acc[4*q+0] += w.x * v; acc[4*q+1] += w.y * v;
            acc[4*q+2] += w.z * v; acc[4*q+3] += w.w * v;
        }
    }
#pragma unroll
    for (int el = 0; el < 48; el++) {
        int e = eg * 48 + el;
        if (e < 96) g_xi[(b*96 + e)*LSP + l] = acc[el];
        else        g_z [(b*96 + (e - 96))*LSP + l] = acc[el];
    }
}

// ---------------- 8) depthwise causal conv1d + SiLU -> xs ----------------
__global__ void k_conv1d(const float* __restrict__ cw, const float* __restrict__ cb) {
    int idx = blockIdx.x * blockDim.x + threadIdx.x;
    if (idx >= NB*DI*LSP) return;
    int l = idx % LSP; int bd = idx / LSP; int d = bd % DI;
    const float* xp = g_xi + bd * LSP;
    float s = __ldg(cb + d);
#pragma unroll
    for (int k = 0; k < 4; k++) {
        int li = l - 3 + k;
        if (li >= 0) s += __ldg(cw + d*4 + k) * xp[li];
    }
    g_xs[idx] = s / (1.f + __expf(-s));
}

// ---------------- 9) x_proj + dt_proj + softplus -> delta, dx, Bm, Cm ----------------
__global__ void __launch_bounds__(128) k_xproj(const float* __restrict__ xw,
                                               const float* __restrict__ dtw,
                                               const float* __restrict__ dtb) {
    __shared__ float sW[35 * 96];
    for (int i = threadIdx.x; i < 35 * 96; i += blockDim.x) sW[i] = xw[i];
    __syncthreads();
    int g = blockIdx.x * blockDim.x + threadIdx.x;
    int l = g % LSP, b = g / LSP;
    float acc[35];
#pragma unroll
    for (int e = 0; e < 35; e++) acc[e] = 0.f;
    for (int ci = 0; ci < 96; ci++) {
        float v = __ldg(g_xs + (b*96 + ci)*LSP + l);
#pragma unroll
        for (int e = 0; e < 35; e++) acc[e] += sW[e*96 + ci] * v;
    }
#pragma unroll
    for (int n = 0; n < 16; n++) {
        g_Bm[(b*LSP + l)*16 + n] = acc[3 + n];
        g_Cm[(b*LSP + l)*16 + n] = acc[19 + n];
    }
    for (int d = 0; d < 96; d++) {
        float t = __ldg(dtb + d) + __ldg(dtw + d*3)     * acc[0]
                                 + __ldg(dtw + d*3 + 1) * acc[1]
                                 + __ldg(dtw + d*3 + 2) * acc[2];
        float dl = (t > 20.f) ? t : log1pf(__expf(t));
        int o = (b*96 + d)*LSP + l;
        g_delta[o] = dl;
        g_dx[o] = dl * g_xs[o];
    }
}

// ---------------- 10) scan phase A: per-chunk (prod dA, h_end) ----------------
__global__ void __launch_bounds__(512) k_scanA(const float* __restrict__ Alog) {
    int b = blockIdx.z, dg = blockIdx.y, ch = blockIdx.x;
    int dl_ = threadIdx.x >> 4, n = threadIdx.x & 15;
    int d = dg * 32 + dl_;
    float A = -__expf(__ldg(Alog + d*16 + n));
    const float* dp = g_delta + (b*96 + d)*LSP + ch*CS;
    const float* xp = g_dx    + (b*96 + d)*LSP + ch*CS;
    const float* Bp = g_Bm + (b*LSP + ch*CS)*16 + n;
    float h = 0.f, P = 1.f;
#pragma unroll 4
    for (int i = 0; i < CS; i++) {
        float dv = __ldg(dp + i);
        float a = __expf(dv * A);
        h = a * h + __ldg(xp + i) * __ldg(Bp + i*16);
        P *= a;
    }
    int si = ((b*NCH + ch)*DI + d)*NS + n;
    g_P[si] = P; g_He[si] = h;
}

// ---------------- 11) scan phase B: serial chunk-carry combine ----------------
__global__ void k_carry() {
    int t = blockIdx.x * blockDim.x + threadIdx.x;
    if (t >= NB*DI*NS) return;
    int b = t / (DI*NS); int r = t % (DI*NS);
    float c = 0.f;
    for (int k = 0; k < NCH; k++) {
        int si = (b*NCH + k)*DI*NS + r;
        g_ca[si] = c;
        c = g_P[si] * c + g_He[si];
    }
}

// ---------------- 12) scan phase C: replay with carry, emit y ----------------
__global__ void __launch_bounds__(512) k_scanC(const float* __restrict__ Alog) {
    int b = blockIdx.z, dg = blockIdx.y, ch = blockIdx.x;
    int dl_ = threadIdx.x >> 4, n = threadIdx.x & 15;
    int d = dg * 32 + dl_;
    float A = -__expf(__ldg(Alog + d*16 + n));
    int si = ((b*NCH + ch)*DI + d)*NS + n;
    float h = g_ca[si];
    const float* dp = g_delta + (b*96 + d)*LSP + ch*CS;
    const float* xp = g_dx    + (b*96 + d)*LSP + ch*CS;
    const float* Bp = g_Bm + (b*LSP + ch*CS)*16 + n;
    const float* Cp = g_Cm + (b*LSP + ch*CS)*16 + n;
    float* yp = g_y + (b*96 + d)*LSP + ch*CS;
    float yreg = 0.f;
#pragma unroll 4
    for (int i = 0; i < CS; i++) {
        float dv = __ldg(dp + i);
        float a = __expf(dv * A);
        h = a * h + __ldg(xp + i) * __ldg(Bp + i*16);
        float p = h * __ldg(Cp + i*16);
        p += __shfl_xor_sync(0xffffffffu, p, 8, 16);
        p += __shfl_xor_sync(0xffffffffu, p, 4, 16);
        p += __shfl_xor_sync(0xffffffffu, p, 2, 16);
        p += __shfl_xor_sync(0xffffffffu, p, 1, 16);
        if ((i & 15) == n) yreg = p;
        if ((i & 15) == 15) yp[(i & ~15) + n] = yreg;
    }
}

// ---------------- 13) epilogue: (y + D*xs)*silu(z) -> out_proj -> + Lx ----------------
__global__ void __launch_bounds__(128) k_epi(const float* __restrict__ Wo,
                                             const float* __restrict__ Dp,
                                             float* __restrict__ outp) {
    __shared__ float sW[96 * 48];             // [d][e]
    for (int i = threadIdx.x; i < 96 * 48; i += blockDim.x) {
        int d = i / 48, e = i % 48;
        sW[i] = Wo[e*96 + d];
    }
    __syncthreads();
    int g = blockIdx.x * blockDim.x + threadIdx.x;
    int l = g % LSP, b = g / LSP;
    float acc[48];
#pragma unroll
    for (int e = 0; e < 48; e++) acc[e] = 0.f;
    for (int d = 0; d < 96; d++) {
        int o = (b*96 + d)*LSP + l;
        float yv = __ldg(g_y + o), xv = __ldg(g_xs + o), zv = __ldg(g_z + o);
        float y2 = (yv + __ldg(Dp + d) * xv) * (zv / (1.f + __expf(-zv)));
        const float4* wp = (const float4*)(sW + d * 48);
#pragma unroll
        for (int q = 0; q < 12; q++) {
            float4 w = wp[q];
            acc[4*q+0] += w.x * y2; acc[4*q+1] += w.y * y2;
            acc[4*q+2] += w.z * y2; acc[4*q+3] += w.w * y2;
        }
    }
#pragma unroll
    for (int e = 0; e < 48; e++) {
        int o = (b*48 + e)*LSP + l;
        outp[o] = acc[e] + g_Lx[o];
    }
}

// ---------------- launcher ----------------
extern "C" void kernel_launch(void* const* d_in, const int* in_sizes, int n_in,
                              void* d_out, int out_size) {
    const float* x    = (const float*)d_in[0];
    const float* Hx   = (const float*)d_in[1];
    const float* W1   = (const float*)d_in[2];
    const float* b1   = (const float*)d_in[3];
    const float* W2   = (const float*)d_in[4];
    const float* b2   = (const float*)d_in[5];
    const float* W3   = (const float*)d_in[6];
    const float* b3   = (const float*)d_in[7];
    const float* Wip  = (const float*)d_in[8];
    const float* cw   = (const float*)d_in[9];
    const float* cb   = (const float*)d_in[10];
    const float* xw   = (const float*)d_in[11];
    const float* dtw  = (const float*)d_in[12];
    const float* dtb  = (const float*)d_in[13];
    const float* Alog = (const float*)d_in[14];
    const float* Dp   = (const float*)d_in[15];
    const float* Wo   = (const float*)d_in[16];
    float* outp = (float*)d_out;

    k_upsample<<<(NB*C0*LSP + 255)/256, 256>>>(x);
    k_conv1<<<(NB*LSP)/128, 128>>>(Hx, W1, b1);
    dim3 g2(9, 6, 6), t2(8, 8, 4);
    k_conv2<<<g2, t2>>>(W2, b2);
    k_conv3<<<(NB*LSP)/128, 128>>>(W3, b3);
    k_stats<<<NB*C0, 256>>>();
    k_selu<<<(NB*C0*LSP + 255)/256, 256>>>();
    dim3 gip(LSP/128, 4, NB);
    k_inproj<<<gip, 128>>>(Wip);
    k_conv1d<<<(NB*DI*LSP + 255)/256, 256>>>(cw, cb);
    k_xproj<<<(NB*LSP)/128, 128>>>(xw, dtw, dtb);
    dim3 gs(NCH, 3, NB);
    k_scanA<<<gs, 512>>>(Alog);
    k_carry<<<(NB*DI*NS + 255)/256, 256>>>();
    k_scanC<<<gs, 512>>>(Alog);
    k_epi<<<(NB*LSP)/128, 128>>>(Wo, Dp, outp);
}

// round 2
// speedup vs baseline: 1.2812x; 1.2812x over previous
#include <cuda_runtime.h>
#include <math.h>

#define LSP 13824            // 24*24*24
#define NB 2
#define C0 48
#define DI 96
#define NS 16
#define NCH 54               // scan chunks
#define CS 256               // chunk size (54*256 = 13824)

// ---------------- scratch ----------------
__device__ float g_up[NB*C0*LSP];
__device__ float g_h1[NB*C0*LSP];
__device__ float g_h2[NB*C0*LSP];
__device__ float g_h3[NB*C0*LSP];
__device__ float g_Lx[NB*C0*LSP];
__device__ float g_mean[NB*C0];
__device__ float g_istd[NB*C0];
__device__ float g_xi[NB*DI*LSP];
__device__ float g_z [NB*DI*LSP];
__device__ float g_xs[NB*DI*LSP];
__device__ float g_delta[NB*DI*LSP];
__device__ float g_Bm[NB*LSP*NS];
__device__ float g_Cm[NB*LSP*NS];
__device__ float g_P [NB*NCH*DI*NS];
__device__ float g_He[NB*NCH*DI*NS];
__device__ float g_ca[NB*NCH*DI*NS];
__device__ float g_y [NB*DI*LSP];

__device__ __forceinline__ float silu(float v) {
    return v / (1.f + __expf(-v));
}

// ---------------- 1) trilinear 2x upsample, align_corners ----------------
__global__ void k_upsample(const float* __restrict__ x) {
    int idx = blockIdx.x * blockDim.x + threadIdx.x;
    if (idx >= NB*C0*LSP) return;
    int t = idx % 24; int r = idx / 24;
    int w = r % 24;  r /= 24;
    int h = r % 24;  r /= 24;          // r = b*48 + c
    const float sc = 11.0f / 23.0f;
    float ph = h * sc, pw = w * sc, pt = t * sc;
    int hl = (int)ph, wl = (int)pw, tl = (int)pt;
    float fh = ph - hl, fw = pw - wl, ft = pt - tl;
    int hh = min(hl + 1, 11), wh = min(wl + 1, 11), th = min(tl + 1, 11);
    const float* bp = x + r * 1728;
    float c000 = bp[hl*144 + wl*12 + tl];
    float c001 = bp[hl*144 + wl*12 + th];
    float c010 = bp[hl*144 + wh*12 + tl];
    float c011 = bp[hl*144 + wh*12 + th];
    float c100 = bp[hh*144 + wl*12 + tl];
    float c101 = bp[hh*144 + wl*12 + th];
    float c110 = bp[hh*144 + wh*12 + tl];
    float c111 = bp[hh*144 + wh*12 + th];
    float v00 = c000 + (c001 - c000) * ft;
    float v01 = c010 + (c011 - c010) * ft;
    float v10 = c100 + (c101 - c100) * ft;
    float v11 = c110 + (c111 - c110) * ft;
    float v0 = v00 + (v01 - v00) * fw;
    float v1 = v10 + (v11 - v10) * fw;
    g_up[idx] = v0 + (v1 - v0) * fh;
}

// ---------------- 2) 1x1 conv concat([up(48), Hx(96)]) -> h1 ----------------
// block 512 = 128 l x 4 co-groups(12 co each); grid (LSP/128, NB)
__global__ void __launch_bounds__(512) k_conv1(const float* __restrict__ Hx,
                                               const float* __restrict__ W1,
                                               const float* __restrict__ b1) {
    __shared__ float sW[144 * 48];            // [ci][co]
    int tid = threadIdx.x;
    for (int i = tid; i < 144 * 48; i += 512) {
        int ci = i / 48, co = i % 48;
        sW[i] = W1[co * 144 + ci];
    }
    __syncthreads();
    int lq = tid & 127, q = tid >> 7;
    int l = blockIdx.x * 128 + lq;
    int b = blockIdx.y;
    float acc[12];
#pragma unroll
    for (int j = 0; j < 12; j++) acc[j] = __ldg(b1 + q*12 + j);
    for (int ci = 0; ci < 144; ci++) {
        float v = (ci < 48) ? __ldg(g_up + (b*48 + ci)*LSP + l)
                            : __ldg(Hx + (b*96 + (ci - 48))*LSP + l);
        const float4* wp = (const float4*)(sW + ci * 48 + q * 12);
#pragma unroll
        for (int p = 0; p < 3; p++) {
            float4 w = wp[p];
            acc[4*p+0] += w.x * v; acc[4*p+1] += w.y * v;
            acc[4*p+2] += w.z * v; acc[4*p+3] += w.w * v;
        }
    }
#pragma unroll
    for (int j = 0; j < 12; j++)
        g_h1[(b*48 + q*12 + j)*LSP + l] = acc[j];
}

// ---------------- 3) 3x3x3 conv, pad 1, 48->48 : h1 -> h2 ----------------
// tile 4(x) x 8(y) x 8(z), block (4,8,4), each thread 2 z's, 16 co
__global__ void __launch_bounds__(128) k_conv2(const float* __restrict__ W2,
                                               const float* __restrict__ b2) {
    __shared__ float sIn[8 * 600];            // 8 ci x (10z x 10y x 6x)
    __shared__ float sW[8 * 27 * 16];         // [ci][k][co]
    int bz = blockIdx.z;                      // b*3 + cog
    int b = bz / 3, cog = bz % 3;
    int zt = blockIdx.y;
    int yt = blockIdx.x / 6, xt = blockIdx.x % 6;
    int z0 = zt * 8, y0 = yt * 8, x0 = xt * 4;
    int tx = threadIdx.x, ty = threadIdx.y, tz = threadIdx.z;
    int tid = (tz * 8 + ty) * 4 + tx;
    float acc0[16], acc1[16];
#pragma unroll
    for (int i = 0; i < 16; i++) { acc0[i] = 0.f; acc1[i] = 0.f; }

    for (int cc = 0; cc < 6; cc++) {
        __syncthreads();
        for (int i = tid; i < 4800; i += 128) {
            int ci = i / 600; int p = i % 600;
            int lz = p / 60; int q2 = p % 60;
            int ly = q2 / 6; int lx = q2 % 6;
            int gz = z0 - 1 + lz, gy = y0 - 1 + ly, gx = x0 - 1 + lx;
            float v = 0.f;
            if (gz >= 0 && gz < 24 && gy >= 0 && gy < 24 && gx >= 0 && gx < 24)
                v = g_h1[(b*48 + cc*8 + ci)*LSP + gz*576 + gy*24 + gx];
            sIn[i] = v;
        }
        for (int i = tid; i < 3456; i += 128) {
            int ci = i / (27 * 16); int k = (i / 16) % 27; int co = i % 16;
            sW[i] = W2[((cog*16 + co)*48 + cc*8 + ci)*27 + k];
        }
        __syncthreads();
#pragma unroll 1
        for (int ci = 0; ci < 8; ci++) {
            const float* ip = sIn + ci*600 + (tz*10 + ty)*6 + tx;
            const float* wp = sW + ci*27*16;
#pragma unroll
            for (int kz = 0; kz < 3; kz++)
#pragma unroll
            for (int ky = 0; ky < 3; ky++)
#pragma unroll
            for (int kx = 0; kx < 3; kx++) {
                float v0 = ip[kz*60 + ky*6 + kx];
                float v1 = ip[(kz+4)*60 + ky*6 + kx];
                const float4* w4 = (const float4*)(wp + (kz*9 + ky*3 + kx)*16);
#pragma unroll
                for (int p = 0; p < 4; p++) {
                    float4 w = w4[p];
                    acc0[4*p+0] += w.x * v0; acc0[4*p+1] += w.y * v0;
                    acc0[4*p+2] += w.z * v0; acc0[4*p+3] += w.w * v0;
                    acc1[4*p+0] += w.x * v1; acc1[4*p+1] += w.y * v1;
                    acc1[4*p+2] += w.z * v1; acc1[4*p+3] += w.w * v1;
                }
            }
        }
    }
    int z1 = z0 + tz, z2 = z1 + 4;
    int y = y0 + ty, x = x0 + tx;
#pragma unroll
    for (int co = 0; co < 16; co++) {
        float bv = __ldg(b2 + cog*16 + co);
        int base = (b*48 + cog*16 + co)*LSP + y*24 + x;
        g_h2[base + z1*576] = acc0[co] + bv;
        g_h2[base + z2*576] = acc1[co] + bv;
    }
}

// ---------------- 4) 1x1 conv 48->48 : h2 -> h3 ----------------
__global__ void __launch_bounds__(512) k_conv3(const float* __restrict__ W3,
                                               const float* __restrict__ b3) {
    __shared__ float sW[48 * 48];
    int tid = threadIdx.x;
    for (int i = tid; i < 48 * 48; i += 512) {
        int ci = i / 48, co = i % 48;
        sW[i] = W3[co * 48 + ci];
    }
    __syncthreads();
    int lq = tid & 127, q = tid >> 7;
    int l = blockIdx.x * 128 + lq;
    int b = blockIdx.y;
    float acc[12];
#pragma unroll
    for (int j = 0; j < 12; j++) acc[j] = __ldg(b3 + q*12 + j);
    for (int ci = 0; ci < 48; ci++) {
        float v = __ldg(g_h2 + (b*48 + ci)*LSP + l);
        const float4* wp = (const float4*)(sW + ci * 48 + q * 12);
#pragma unroll
        for (int p = 0; p < 3; p++) {
            float4 w = wp[p];
            acc[4*p+0] += w.x * v; acc[4*p+1] += w.y * v;
            acc[4*p+2] += w.z * v; acc[4*p+3] += w.w * v;
        }
    }
#pragma unroll
    for (int j = 0; j < 12; j++)
        g_h3[(b*48 + q*12 + j)*LSP + l] = acc[j];
}

// ---------------- 5) instance-norm stats ----------------
__global__ void k_stats() {
    int bc = blockIdx.x;                      // 0..95
    const float* p = g_h3 + bc * LSP;
    float s1 = 0.f, s2 = 0.f;
    for (int i = threadIdx.x; i < LSP; i += blockDim.x) {
        float v = p[i]; s1 += v; s2 += v * v;
    }
    __shared__ float r1[256], r2[256];
    r1[threadIdx.x] = s1; r2[threadIdx.x] = s2; __syncthreads();
    for (int s = 128; s > 0; s >>= 1) {
        if (threadIdx.x < s) { r1[threadIdx.x] += r1[threadIdx.x + s];
                               r2[threadIdx.x] += r2[threadIdx.x + s]; }
        __syncthreads();
    }
    if (threadIdx.x == 0) {
        float m = r1[0] / (float)LSP;
        float var = r2[0] / (float)LSP - m * m;
        g_mean[bc] = m;
        g_istd[bc] = rsqrtf(var + 1e-5f);
    }
}

// ---------------- 6) normalize + SELU -> Lx ----------------
__global__ void k_selu() {
    int idx = blockIdx.x * blockDim.x + threadIdx.x;
    if (idx >= NB*C0*LSP) return;
    int bc = idx / LSP;
    float v = (g_h3[idx] - g_mean[bc]) * g_istd[bc];
    const float a = 1.6732632423543772f, s = 1.0507009873554805f;
    g_Lx[idx] = (v > 0.f) ? s * v : s * a * expm1f(v);
}

// ---------------- 7) in_proj 48 -> 192 (split xi / z) ----------------
// block 512 = 32 l x 16 q(12 co each); grid (LSP/32, NB)
__global__ void __launch_bounds__(512) k_inproj(const float* __restrict__ Wip) {
    __shared__ float sW[48 * 192];            // [ci][e]
    int tid = threadIdx.x;
    for (int i = tid; i < 48 * 192; i += 512) {
        int ci = i / 192, e = i % 192;
        sW[i] = Wip[e * 48 + ci];
    }
    __syncthreads();
    int lq = tid & 31, q = tid >> 5;          // q 0..15
    int l = blockIdx.x * 32 + lq;
    int b = blockIdx.y;
    float acc[12];
#pragma unroll
    for (int j = 0; j < 12; j++) acc[j] = 0.f;
    for (int ci = 0; ci < 48; ci++) {
        float v = __ldg(g_Lx + (b*48 + ci)*LSP + l);
        const float4* wp = (const float4*)(sW + ci * 192 + q * 12);
#pragma unroll
        for (int p = 0; p < 3; p++) {
            float4 w = wp[p];
            acc[4*p+0] += w.x * v; acc[4*p+1] += w.y * v;
            acc[4*p+2] += w.z * v; acc[4*p+3] += w.w * v;
        }
    }
#pragma unroll
    for (int j = 0; j < 12; j++) {
        int e = q * 12 + j;
        if (e < 96) g_xi[(b*96 + e)*LSP + l] = acc[j];
        else        g_z [(b*96 + (e - 96))*LSP + l] = acc[j];
    }
}

// ---------------- 8) fused conv1d+SiLU -> xs, x_proj, dt_proj+softplus ----------------
// block 512, tile of 64 l; grid (LSP/64, NB)
__global__ void __launch_bounds__(512) k_xproj(const float* __restrict__ cw,
                                               const float* __restrict__ cb,
                                               const float* __restrict__ xw,
                                               const float* __restrict__ dtw,
                                               const float* __restrict__ dtb) {
    __shared__ float sxs[96 * 64];            // [d][l]
    __shared__ float sWx[40 * 96];            // [e][ci], rows 35..39 zero
    __shared__ float sdt[64 * 3];
    int tid = threadIdx.x;
    int b = blockIdx.y;
    int l0 = blockIdx.x * 64;
    for (int i = tid; i < 40 * 96; i += 512)
        sWx[i] = (i < 35 * 96) ? xw[i] : 0.f;
    // phase 1: depthwise causal conv1d + SiLU -> sxs + g_xs
    for (int i = tid; i < 96 * 64; i += 512) {
        int d = i >> 6, lq = i & 63;
        int l = l0 + lq;
        const float* xp = g_xi + (b*96 + d)*LSP;
        float s = __ldg(cb + d);
#pragma unroll
        for (int k = 0; k < 4; k++) {
            int li = l - 3 + k;
            if (li >= 0) s += __ldg(cw + d*4 + k) * __ldg(xp + li);
        }
        float xv = silu(s);
        sxs[i] = xv;
        g_xs[(b*96 + d)*LSP + l] = xv;
    }
    __syncthreads();
    // phase 2: x_proj GEMM (35 outputs, 8 q-groups x 5)
    int lq = tid & 63, q = tid >> 6;          // q 0..7
    int l = l0 + lq;
    float acc[5];
#pragma unroll
    for (int j = 0; j < 5; j++) acc[j] = 0.f;
    for (int ci = 0; ci < 96; ci++) {
        float v = sxs[ci * 64 + lq];
#pragma unroll
        for (int j = 0; j < 5; j++)
            acc[j] += sWx[(q*5 + j)*96 + ci] * v;
    }
#pragma unroll
    for (int j = 0; j < 5; j++) {
        int e = q*5 + j;
        if (e < 3)            sdt[lq*3 + e] = acc[j];
        else if (e < 19)      g_Bm[(b*LSP + l)*16 + (e - 3)]  = acc[j];
        else if (e < 35)      g_Cm[(b*LSP + l)*16 + (e - 19)] = acc[j];
    }
    __syncthreads();
    // phase 3: dt_proj + softplus -> delta
    for (int i = tid; i < 96 * 64; i += 512) {
        int d = i >> 6, lq2 = i & 63;
        float t = __ldg(dtb + d) + __ldg(dtw + d*3)     * sdt[lq2*3]
                                 + __ldg(dtw + d*3 + 1) * sdt[lq2*3 + 1]
                                 + __ldg(dtw + d*3 + 2) * sdt[lq2*3 + 2];
        float dl = (t > 20.f) ? t : log1pf(__expf(t));
        g_delta[(b*96 + d)*LSP + l0 + lq2] = dl;
    }
}

// ---------------- 9) scan phase A: per-chunk (prod dA, h_end) ----------------
__global__ void __launch_bounds__(512) k_scanA(const float* __restrict__ Alog) {
    int b = blockIdx.z, dg = blockIdx.y, ch = blockIdx.x;
    int dl_ = threadIdx.x >> 4, n = threadIdx.x & 15;
    int d = dg * 32 + dl_;
    float A = -__expf(__ldg(Alog + d*16 + n));
    const float* dp = g_delta + (b*96 + d)*LSP + ch*CS;
    const float* xp = g_xs    + (b*96 + d)*LSP + ch*CS;
    const float* Bp = g_Bm + (b*LSP + ch*CS)*16 + n;
    float h = 0.f, P = 1.f;
#pragma unroll 4
    for (int i = 0; i < CS; i++) {
        float dv = __ldg(dp + i);
        float a = __expf(dv * A);
        h = a * h + (dv * __ldg(xp + i)) * __ldg(Bp + i*16);
        P *= a;
    }
    int si = ((b*NCH + ch)*DI + d)*NS + n;
    g_P[si] = P; g_He[si] = h;
}

// ---------------- 10) scan phase B: serial chunk-carry combine ----------------
__global__ void k_carry() {
    int t = blockIdx.x * blockDim.x + threadIdx.x;
    if (t >= NB*DI*NS) return;
    int b = t / (DI*NS); int r = t % (DI*NS);
    float c = 0.f;
    for (int k = 0; k < NCH; k++) {
        int si = (b*NCH + k)*DI*NS + r;
        g_ca[si] = c;
        c = g_P[si] * c + g_He[si];
    }
}

// ---------------- 11) scan phase C: replay with carry, emit y ----------------
__global__ void __launch_bounds__(512) k_scanC(const float* __restrict__ Alog) {
    int b = blockIdx.z, dg = blockIdx.y, ch = blockIdx.x;
    int dl_ = threadIdx.x >> 4, n = threadIdx.x & 15;
    int d = dg * 32 + dl_;
    float A = -__expf(__ldg(Alog + d*16 + n));
    int si = ((b*NCH + ch)*DI + d)*NS + n;
    float h = g_ca[si];
    const float* dp = g_delta + (b*96 + d)*LSP + ch*CS;
    const float* xp = g_xs    + (b*96 + d)*LSP + ch*CS;
    const float* Bp = g_Bm + (b*LSP + ch*CS)*16 + n;
    const float* Cp = g_Cm + (b*LSP + ch*CS)*16 + n;
    float* yp = g_y + (b*96 + d)*LSP + ch*CS;
    float yreg = 0.f;
#pragma unroll 4
    for (int i = 0; i < CS; i++) {
        float dv = __ldg(dp + i);
        float a = __expf(dv * A);
        h = a * h + (dv * __ldg(xp + i)) * __ldg(Bp + i*16);
        float p = h * __ldg(Cp + i*16);
        p += __shfl_xor_sync(0xffffffffu, p, 8, 16);
        p += __shfl_xor_sync(0xffffffffu, p, 4, 16);
        p += __shfl_xor_sync(0xffffffffu, p, 2, 16);
        p += __shfl_xor_sync(0xffffffffu, p, 1, 16);
        if ((i & 15) == n) yreg = p;
        if ((i & 15) == 15) yp[(i & ~15) + n] = yreg;
    }
}

// ---------------- 12) epilogue: (y + D*xs)*silu(z) -> out_proj -> + Lx ----------------
// block 512 = 64 l x 8 q(6 co each); grid (LSP/64, NB)
__global__ void __launch_bounds__(512) k_epi(const float* __restrict__ Wo,
                                             const float* __restrict__ Dp,
                                             float* __restrict__ outp) {
    __shared__ float sy2[96 * 64];            // [d][l]
    __shared__ float sW[96 * 48];             // [d][e]
    int tid = threadIdx.x;
    int b = blockIdx.y;
    int l0 = blockIdx.x * 64;
    for (int i = tid; i < 96 * 48; i += 512) {
        int d = i / 48, e = i % 48;
        sW[i] = Wo[e*96 + d];
    }
    // phase 1: gated y2 into smem
    for (int i = tid; i < 96 * 64; i += 512) {
        int d = i >> 6, lq = i & 63;
        int o = (b*96 + d)*LSP + l0 + lq;
        float yv = __ldg(g_y + o), xv = __ldg(g_xs + o), zv = __ldg(g_z + o);
        sy2[i] = (yv + __ldg(Dp + d) * xv) * silu(zv);
    }
    __syncthreads();
    // phase 2: out_proj GEMM + residual
    int lq = tid & 63, q = tid >> 6;          // q 0..7, 6 co each
    int l = l0 + lq;
    float acc[6];
#pragma unroll
    for (int j = 0; j < 6; j++) acc[j] = 0.f;
    for (int d = 0; d < 96; d++) {
        float v = sy2[d * 64 + lq];
        const float2* wp = (const float2*)(sW + d * 48 + q * 6);
#pragma unroll
        for (int p = 0; p < 3; p++) {
            float2 w = wp[p];
            acc[2*p+0] += w.x * v; acc[2*p+1] += w.y * v;
        }
    }
#pragma unroll
    for (int j = 0; j < 6; j++) {
        int e = q * 6 + j;
        int o = (b*48 + e)*LSP + l;
        outp[o] = acc[j] + __ldg(g_Lx + o);
    }
}

// ---------------- launcher ----------------
extern "C" void kernel_launch(void* const* d_in, const int* in_sizes, int n_in,
                              void* d_out, int out_size) {
    const float* x    = (const float*)d_in[0];
    const float* Hx   = (const float*)d_in[1];
    const float* W1   = (const float*)d_in[2];
    const float* b1   = (const float*)d_in[3];
    const float* W2   = (const float*)d_in[4];
    const float* b2   = (const float*)d_in[5];
    const float* W3   = (const float*)d_in[6];
    const float* b3   = (const float*)d_in[7];
    const float* Wip  = (const float*)d_in[8];
    const float* cw   = (const float*)d_in[9];
    const float* cb   = (const float*)d_in[10];
    const float* xw   = (const float*)d_in[11];
    const float* dtw  = (const float*)d_in[12];
    const float* dtb  = (const float*)d_in[13];
    const float* Alog = (const float*)d_in[14];
    const float* Dp   = (const float*)d_in[15];
    const float* Wo   = (const float*)d_in[16];
    float* outp = (float*)d_out;

    k_upsample<<<(NB*C0*LSP + 255)/256, 256>>>(x);
    k_conv1<<<dim3(LSP/128, NB), 512>>>(Hx, W1, b1);
    dim3 g2(18, 3, 6), t2(4, 8, 4);
    k_conv2<<<g2, t2>>>(W2, b2);
    k_conv3<<<dim3(LSP/128, NB), 512>>>(W3, b3);
    k_stats<<<NB*C0, 256>>>();
    k_selu<<<(NB*C0*LSP + 255)/256, 256>>>();
    k_inproj<<<dim3(LSP/32, NB), 512>>>(Wip);
    k_xproj<<<dim3(LSP/64, NB), 512>>>(cw, cb, xw, dtw, dtb);
    dim3 gs(NCH, 3, NB);
    k_scanA<<<gs, 512>>>(Alog);
    k_carry<<<(NB*DI*NS + 255)/256, 256>>>();
    k_scanC<<<gs, 512>>>(Alog);
    k_epi<<<dim3(LSP/64, NB), 512>>>(Wo, Dp, outp);
}

// round 3
// speedup vs baseline: 1.4206x; 1.1088x over previous
#include <cuda_runtime.h>
#include <math.h>

#define LSP 13824            // 24*24*24
#define NB 2
#define C0 48
#define DI 96
#define NS 16
#define NCH 54               // scan chunks
#define CS 256               // chunk size (54*256 = 13824)

// ---------------- scratch ----------------
__device__ float g_h1[NB*C0*LSP];
__device__ float g_h2[NB*C0*LSP];
__device__ float g_h3[NB*C0*LSP];
__device__ float g_Lx[NB*C0*LSP];
__device__ float g_s1[NB*C0];
__device__ float g_s2[NB*C0];
__device__ float g_xi[NB*DI*LSP];
__device__ float g_z [NB*DI*LSP];
__device__ float g_xs[NB*DI*LSP];
__device__ float g_delta[NB*DI*LSP];
__device__ float g_Bm[NB*LSP*NS];
__device__ float g_Cm[NB*LSP*NS];
__device__ float g_P [NB*NCH*DI*NS];
__device__ float g_He[NB*NCH*DI*NS];
__device__ float g_y [NB*DI*LSP];

__device__ __forceinline__ float silu(float v) {
    return v / (1.f + __expf(-v));
}

// ---------------- 1) fused upsample + 1x1 conv (144->48) -> h1 ----------------
// grid (LSP/64, NB), block 512 = 64 l x 8 q (6 co each)
__global__ void __launch_bounds__(512) k_conv1(const float* __restrict__ x,
                                               const float* __restrict__ Hx,
                                               const float* __restrict__ W1,
                                               const float* __restrict__ b1) {
    __shared__ float sW[144 * 48];            // [ci][co]  27.6KB
    __shared__ float sUp[48 * 64];            // [ci][lq]  12KB
    int tid = threadIdx.x;
    int b = blockIdx.y;
    int l0 = blockIdx.x * 64;
    if (blockIdx.x == 0 && b == 0 && tid < NB*C0) { g_s1[tid] = 0.f; g_s2[tid] = 0.f; }
    for (int i = tid; i < 144 * 48; i += 512) {
        int ci = i / 48, co = i % 48;
        sW[i] = W1[co * 144 + ci];
    }
    // trilinear upsample of x into smem
    for (int i = tid; i < 48 * 64; i += 512) {
        int ci = i >> 6, lq = i & 63;
        int l = l0 + lq;
        int t = l % 24, w = (l / 24) % 24, h = l / 576;
        const float sc = 11.0f / 23.0f;
        float ph = h * sc, pw = w * sc, pt = t * sc;
        int hl = (int)ph, wl = (int)pw, tl = (int)pt;
        float fh = ph - hl, fw = pw - wl, ft = pt - tl;
        int hh = min(hl + 1, 11), wh = min(wl + 1, 11), th = min(tl + 1, 11);
        const float* bp = x + (b * 48 + ci) * 1728;
        float c000 = bp[hl*144 + wl*12 + tl];
        float c001 = bp[hl*144 + wl*12 + th];
        float c010 = bp[hl*144 + wh*12 + tl];
        float c011 = bp[hl*144 + wh*12 + th];
        float c100 = bp[hh*144 + wl*12 + tl];
        float c101 = bp[hh*144 + wl*12 + th];
        float c110 = bp[hh*144 + wh*12 + tl];
        float c111 = bp[hh*144 + wh*12 + th];
        float v00 = c000 + (c001 - c000) * ft;
        float v01 = c010 + (c011 - c010) * ft;
        float v10 = c100 + (c101 - c100) * ft;
        float v11 = c110 + (c111 - c110) * ft;
        float v0 = v00 + (v01 - v00) * fw;
        float v1 = v10 + (v11 - v10) * fw;
        sUp[i] = v0 + (v1 - v0) * fh;
    }
    __syncthreads();
    int lq = tid & 63, q = tid >> 6;          // q 0..7, 6 co each
    int l = l0 + lq;
    float acc[6];
#pragma unroll
    for (int j = 0; j < 6; j++) acc[j] = __ldg(b1 + q*6 + j);
    for (int ci = 0; ci < 144; ci++) {
        float v = (ci < 48) ? sUp[ci * 64 + lq]
                            : __ldg(Hx + (b*96 + (ci - 48))*LSP + l);
        const float2* wp = (const float2*)(sW + ci * 48 + q * 6);
#pragma unroll
        for (int p = 0; p < 3; p++) {
            float2 w = wp[p];
            acc[2*p+0] += w.x * v; acc[2*p+1] += w.y * v;
        }
    }
#pragma unroll
    for (int j = 0; j < 6; j++)
        g_h1[(b*48 + q*6 + j)*LSP + l] = acc[j];
}

// ---------------- 2) 3x3x3 conv, pad 1, 48->48 : h1 -> h2 ----------------
// tile 4(x) x 8(y) x 8(z), block (4,8,4) = 128, 2 z per thread, 8 co per block
__global__ void __launch_bounds__(128) k_conv2(const float* __restrict__ W2,
                                               const float* __restrict__ b2) {
    __shared__ float sIn[8 * 600];            // 8 ci x (10z x 10y x 6x)  19.2KB
    __shared__ float sW[8 * 27 * 8];          // [ci][k][co]              6.9KB
    int bz = blockIdx.z;                      // b*6 + cog
    int b = bz / 6, cog = bz % 6;
    int zt = blockIdx.y;
    int yt = blockIdx.x / 6, xt = blockIdx.x % 6;
    int z0 = zt * 8, y0 = yt * 8, x0 = xt * 4;
    int tx = threadIdx.x, ty = threadIdx.y, tz = threadIdx.z;
    int tid = (tz * 8 + ty) * 4 + tx;
    float acc0[8], acc1[8];
#pragma unroll
    for (int i = 0; i < 8; i++) { acc0[i] = 0.f; acc1[i] = 0.f; }

    for (int cc = 0; cc < 6; cc++) {
        __syncthreads();
        for (int i = tid; i < 4800; i += 128) {
            int ci = i / 600; int p = i % 600;
            int lz = p / 60; int q2 = p % 60;
            int ly = q2 / 6; int lx = q2 % 6;
            int gz = z0 - 1 + lz, gy = y0 - 1 + ly, gx = x0 - 1 + lx;
            float v = 0.f;
            if (gz >= 0 && gz < 24 && gy >= 0 && gy < 24 && gx >= 0 && gx < 24)
                v = g_h1[(b*48 + cc*8 + ci)*LSP + gz*576 + gy*24 + gx];
            sIn[i] = v;
        }
        for (int i = tid; i < 1728; i += 128) {
            int ci = i / 216; int k = (i / 8) % 27; int co = i % 8;
            sW[i] = W2[((cog*8 + co)*48 + cc*8 + ci)*27 + k];
        }
        __syncthreads();
#pragma unroll 1
        for (int ci = 0; ci < 8; ci++) {
            const float* ip = sIn + ci*600 + (tz*10 + ty)*6 + tx;
            const float* wp = sW + ci*27*8;
#pragma unroll
            for (int kz = 0; kz < 3; kz++)
#pragma unroll
            for (int ky = 0; ky < 3; ky++)
#pragma unroll
            for (int kx = 0; kx < 3; kx++) {
                float v0 = ip[kz*60 + ky*6 + kx];
                float v1 = ip[(kz+4)*60 + ky*6 + kx];
                const float4* w4 = (const float4*)(wp + (kz*9 + ky*3 + kx)*8);
#pragma unroll
                for (int p = 0; p < 2; p++) {
                    float4 w = w4[p];
                    acc0[4*p+0] += w.x * v0; acc0[4*p+1] += w.y * v0;
                    acc0[4*p+2] += w.z * v0; acc0[4*p+3] += w.w * v0;
                    acc1[4*p+0] += w.x * v1; acc1[4*p+1] += w.y * v1;
                    acc1[4*p+2] += w.z * v1; acc1[4*p+3] += w.w * v1;
                }
            }
        }
    }
    int z1 = z0 + tz, z2 = z1 + 4;
    int y = y0 + ty, xg = x0 + tx;
#pragma unroll
    for (int co = 0; co < 8; co++) {
        float bv = __ldg(b2 + cog*8 + co);
        int base = (b*48 + cog*8 + co)*LSP + y*24 + xg;
        g_h2[base + z1*576] = acc0[co] + bv;
        g_h2[base + z2*576] = acc1[co] + bv;
    }
}

// ---------------- 3) 1x1 conv 48->48 + instance-norm partial stats ----------------
// grid (LSP/64, NB), block 512 = 64 l x 8 q (6 co each)
__global__ void __launch_bounds__(512) k_conv3(const float* __restrict__ W3,
                                               const float* __restrict__ b3) {
    __shared__ float sW[48 * 48];             // 9.2KB
    __shared__ float sIn[48 * 64];            // 12KB
    int tid = threadIdx.x;
    int b = blockIdx.y;
    int l0 = blockIdx.x * 64;
    for (int i = tid; i < 48 * 48; i += 512) {
        int ci = i / 48, co = i % 48;
        sW[i] = W3[co * 48 + ci];
    }
    for (int i = tid; i < 48 * 64; i += 512) {
        int ci = i >> 6, lq = i & 63;
        sIn[i] = g_h2[(b*48 + ci)*LSP + l0 + lq];
    }
    __syncthreads();
    int lq = tid & 63, q = tid >> 6;
    int l = l0 + lq;
    float acc[6];
#pragma unroll
    for (int j = 0; j < 6; j++) acc[j] = __ldg(b3 + q*6 + j);
    for (int ci = 0; ci < 48; ci++) {
        float v = sIn[ci * 64 + lq];
        const float2* wp = (const float2*)(sW + ci * 48 + q * 6);
#pragma unroll
        for (int p = 0; p < 3; p++) {
            float2 w = wp[p];
            acc[2*p+0] += w.x * v; acc[2*p+1] += w.y * v;
        }
    }
    int lane = tid & 31;
#pragma unroll
    for (int j = 0; j < 6; j++) {
        int co = q*6 + j;
        g_h3[(b*48 + co)*LSP + l] = acc[j];
        float r1 = acc[j], r2 = acc[j] * acc[j];
#pragma unroll
        for (int s = 16; s > 0; s >>= 1) {
            r1 += __shfl_xor_sync(0xffffffffu, r1, s);
            r2 += __shfl_xor_sync(0xffffffffu, r2, s);
        }
        if (lane == 0) {
            atomicAdd(&g_s1[b*48 + co], r1);
            atomicAdd(&g_s2[b*48 + co], r2);
        }
    }
}

// ---------------- 4) instance-norm finalize + SELU + in_proj 48->192 ----------------
// grid (LSP/48, NB), block 384 = 48 l x 8 q (24 e each)
__global__ void __launch_bounds__(384) k_selu_inproj(const float* __restrict__ Wip) {
    __shared__ float sW[48 * 192];            // [ci][e] 36.9KB
    __shared__ float sLx[48 * 48];            // [ci][lq] 9.2KB
    int tid = threadIdx.x;
    int b = blockIdx.y;
    int l0 = blockIdx.x * 48;
    for (int i = tid; i < 48 * 192; i += 384) {
        int ci = i / 192, e = i % 192;
        sW[i] = Wip[e * 48 + ci];
    }
    const float inv = 1.0f / (float)LSP;
    const float a_ = 1.6732632423543772f, s_ = 1.0507009873554805f;
    for (int i = tid; i < 48 * 48; i += 384) {
        int ci = i / 48, lq = i % 48;
        int bc = b*48 + ci;
        float m = g_s1[bc] * inv;
        float var = g_s2[bc] * inv - m * m;
        float istd = rsqrtf(var + 1e-5f);
        float v = (g_h3[bc*LSP + l0 + lq] - m) * istd;
        float sv = (v > 0.f) ? s_ * v : s_ * a_ * expm1f(v);
        sLx[i] = sv;
        g_Lx[bc*LSP + l0 + lq] = sv;
    }
    __syncthreads();
    int lq = tid % 48, q = tid / 48;          // q 0..7, 24 e each
    int l = l0 + lq;
    float acc[24];
#pragma unroll
    for (int j = 0; j < 24; j++) acc[j] = 0.f;
    for (int ci = 0; ci < 48; ci++) {
        float v = sLx[ci * 48 + lq];
        const float4* wp = (const float4*)(sW + ci * 192 + q * 24);
#pragma unroll
        for (int p = 0; p < 6; p++) {
            float4 w = wp[p];
            acc[4*p+0] += w.x * v; acc[4*p+1] += w.y * v;
            acc[4*p+2] += w.z * v; acc[4*p+3] += w.w * v;
        }
    }
#pragma unroll
    for (int j = 0; j < 24; j++) {
        int e = q * 24 + j;
        if (e < 96) g_xi[(b*96 + e)*LSP + l] = acc[j];
        else        g_z [(b*96 + (e - 96))*LSP + l] = acc[j];
    }
}

// ---------------- 5) fused conv1d+SiLU -> xs, x_proj, dt_proj+softplus ----------------
// block 512, tile of 64 l; grid (LSP/64, NB)
__global__ void __launch_bounds__(512) k_xproj(const float* __restrict__ cw,
                                               const float* __restrict__ cb,
                                               const float* __restrict__ xw,
                                               const float* __restrict__ dtw,
                                               const float* __restrict__ dtb) {
    __shared__ float sxs[96 * 64];            // [d][l]  24KB
    __shared__ float sWx[40 * 96];            // [e][ci] 15.4KB
    __shared__ float sdt[64 * 3];
    int tid = threadIdx.x;
    int b = blockIdx.y;
    int l0 = blockIdx.x * 64;
    for (int i = tid; i < 40 * 96; i += 512)
        sWx[i] = (i < 35 * 96) ? xw[i] : 0.f;
    for (int i = tid; i < 96 * 64; i += 512) {
        int d = i >> 6, lq = i & 63;
        int l = l0 + lq;
        const float* xp = g_xi + (b*96 + d)*LSP;
        float s = __ldg(cb + d);
#pragma unroll
        for (int k = 0; k < 4; k++) {
            int li = l - 3 + k;
            if (li >= 0) s += __ldg(cw + d*4 + k) * __ldg(xp + li);
        }
        float xv = silu(s);
        sxs[i] = xv;
        g_xs[(b*96 + d)*LSP + l] = xv;
    }
    __syncthreads();
    int lq = tid & 63, q = tid >> 6;          // q 0..7
    int l = l0 + lq;
    float acc[5];
#pragma unroll
    for (int j = 0; j < 5; j++) acc[j] = 0.f;
    for (int ci = 0; ci < 96; ci++) {
        float v = sxs[ci * 64 + lq];
#pragma unroll
        for (int j = 0; j < 5; j++)
            acc[j] += sWx[(q*5 + j)*96 + ci] * v;
    }
#pragma unroll
    for (int j = 0; j < 5; j++) {
        int e = q*5 + j;
        if (e < 3)            sdt[lq*3 + e] = acc[j];
        else if (e < 19)      g_Bm[(b*LSP + l)*16 + (e - 3)]  = acc[j];
        else if (e < 35)      g_Cm[(b*LSP + l)*16 + (e - 19)] = acc[j];
    }
    __syncthreads();
    for (int i = tid; i < 96 * 64; i += 512) {
        int d = i >> 6, lq2 = i & 63;
        float t = __ldg(dtb + d) + __ldg(dtw + d*3)     * sdt[lq2*3]
                                 + __ldg(dtw + d*3 + 1) * sdt[lq2*3 + 1]
                                 + __ldg(dtw + d*3 + 2) * sdt[lq2*3 + 2];
        float dl = (t > 20.f) ? t : log1pf(__expf(t));
        g_delta[(b*96 + d)*LSP + l0 + lq2] = dl;
    }
}

// ---------------- 6) scan phase A: per-chunk (prod dA, h_end) ----------------
__global__ void __launch_bounds__(512) k_scanA(const float* __restrict__ Alog) {
    int b = blockIdx.z, dg = blockIdx.y, ch = blockIdx.x;
    int dl_ = threadIdx.x >> 4, n = threadIdx.x & 15;
    int d = dg * 32 + dl_;
    float A = -__expf(__ldg(Alog + d*16 + n));
    const float* dp = g_delta + (b*96 + d)*LSP + ch*CS;
    const float* xp = g_xs    + (b*96 + d)*LSP + ch*CS;
    const float* Bp = g_Bm + (b*LSP + ch*CS)*16 + n;
    float h = 0.f, P = 1.f;
#pragma unroll 4
    for (int i = 0; i < CS; i++) {
        float dv = __ldg(dp + i);
        float a = __expf(dv * A);
        h = a * h + (dv * __ldg(xp + i)) * __ldg(Bp + i*16);
        P *= a;
    }
    int si = ((b*NCH + ch)*DI + d)*NS + n;
    g_P[si] = P; g_He[si] = h;
}

// ---------------- 7) scan phase C: inline carry + replay, emit y ----------------
__global__ void __launch_bounds__(512) k_scanC(const float* __restrict__ Alog) {
    int b = blockIdx.z, dg = blockIdx.y, ch = blockIdx.x;
    int dl_ = threadIdx.x >> 4, n = threadIdx.x & 15;
    int d = dg * 32 + dl_;
    float A = -__expf(__ldg(Alog + d*16 + n));
    // carry-in: combine all previous chunks
    float h = 0.f;
    for (int k = 0; k < ch; k++) {
        int si = ((b*NCH + k)*DI + d)*NS + n;
        h = g_P[si] * h + g_He[si];
    }
    const float* dp = g_delta + (b*96 + d)*LSP + ch*CS;
    const float* xp = g_xs    + (b*96 + d)*LSP + ch*CS;
    const float* Bp = g_Bm + (b*LSP + ch*CS)*16 + n;
    const float* Cp = g_Cm + (b*LSP + ch*CS)*16 + n;
    float* yp = g_y + (b*96 + d)*LSP + ch*CS;
    float yreg = 0.f;
#pragma unroll 4
    for (int i = 0; i < CS; i++) {
        float dv = __ldg(dp + i);
        float a = __expf(dv * A);
        h = a * h + (dv * __ldg(xp + i)) * __ldg(Bp + i*16);
        float p = h * __ldg(Cp + i*16);
        p += __shfl_xor_sync(0xffffffffu, p, 8, 16);
        p += __shfl_xor_sync(0xffffffffu, p, 4, 16);
        p += __shfl_xor_sync(0xffffffffu, p, 2, 16);
        p += __shfl_xor_sync(0xffffffffu, p, 1, 16);
        if ((i & 15) == n) yreg = p;
        if ((i & 15) == 15) yp[(i & ~15) + n] = yreg;
    }
}

// ---------------- 8) epilogue: (y + D*xs)*silu(z) -> out_proj -> + Lx ----------------
// block 512 = 64 l x 8 q(6 co each); grid (LSP/64, NB)
__global__ void __launch_bounds__(512) k_epi(const float* __restrict__ Wo,
                                             const float* __restrict__ Dp,
                                             float* __restrict__ outp) {
    __shared__ float sy2[96 * 64];            // [d][l] 24KB
    __shared__ float sW[96 * 48];             // [d][e] 18KB
    int tid = threadIdx.x;
    int b = blockIdx.y;
    int l0 = blockIdx.x * 64;
    for (int i = tid; i < 96 * 48; i += 512) {
        int d = i / 48, e = i % 48;
        sW[i] = Wo[e*96 + d];
    }
    for (int i = tid; i < 96 * 64; i += 512) {
        int d = i >> 6, lq = i & 63;
        int o = (b*96 + d)*LSP + l0 + lq;
        float yv = __ldg(g_y + o), xv = __ldg(g_xs + o), zv = __ldg(g_z + o);
        sy2[i] = (yv + __ldg(Dp + d) * xv) * silu(zv);
    }
    __syncthreads();
    int lq = tid & 63, q = tid >> 6;          // q 0..7, 6 co each
    int l = l0 + lq;
    float acc[6];
#pragma unroll
    for (int j = 0; j < 6; j++) acc[j] = 0.f;
    for (int d = 0; d < 96; d++) {
        float v = sy2[d * 64 + lq];
        const float2* wp = (const float2*)(sW + d * 48 + q * 6);
#pragma unroll
        for (int p = 0; p < 3; p++) {
            float2 w = wp[p];
            acc[2*p+0] += w.x * v; acc[2*p+1] += w.y * v;
        }
    }
#pragma unroll
    for (int j = 0; j < 6; j++) {
        int e = q * 6 + j;
        int o = (b*48 + e)*LSP + l;
        outp[o] = acc[j] + __ldg(g_Lx + o);
    }
}

// ---------------- launcher ----------------
extern "C" void kernel_launch(void* const* d_in, const int* in_sizes, int n_in,
                              void* d_out, int out_size) {
    const float* x    = (const float*)d_in[0];
    const float* Hx   = (const float*)d_in[1];
    const float* W1   = (const float*)d_in[2];
    const float* b1   = (const float*)d_in[3];
    const float* W2   = (const float*)d_in[4];
    const float* b2   = (const float*)d_in[5];
    const float* W3   = (const float*)d_in[6];
    const float* b3   = (const float*)d_in[7];
    const float* Wip  = (const float*)d_in[8];
    const float* cw   = (const float*)d_in[9];
    const float* cb   = (const float*)d_in[10];
    const float* xw   = (const float*)d_in[11];
    const float* dtw  = (const float*)d_in[12];
    const float* dtb  = (const float*)d_in[13];
    const float* Alog = (const float*)d_in[14];
    const float* Dp   = (const float*)d_in[15];
    const float* Wo   = (const float*)d_in[16];
    float* outp = (float*)d_out;

    k_conv1<<<dim3(LSP/64, NB), 512>>>(x, Hx, W1, b1);
    dim3 g2(18, 3, 12), t2(4, 8, 4);
    k_conv2<<<g2, t2>>>(W2, b2);
    k_conv3<<<dim3(LSP/64, NB), 512>>>(W3, b3);
    k_selu_inproj<<<dim3(LSP/48, NB), 384>>>(Wip);
    k_xproj<<<dim3(LSP/64, NB), 512>>>(cw, cb, xw, dtw, dtb);
    dim3 gs(NCH, 3, NB);
    k_scanA<<<gs, 512>>>(Alog);
    k_scanC<<<gs, 512>>>(Alog);
    k_epi<<<dim3(LSP/64, NB), 512>>>(Wo, Dp, outp);
}

// round 4
// speedup vs baseline: 1.4755x; 1.0387x over previous
#include <cuda_runtime.h>
#include <math.h>

#define LSP 13824            // 24*24*24
#define NB 2
#define C0 48
#define DI 96
#define NS 16
#define NCH 54               // scan chunks
#define CS 256               // chunk size (54*256 = 13824)

// ---------------- scratch ----------------
__device__ float g_h1[NB*C0*LSP];
__device__ float g_h2[NB*C0*LSP];
__device__ float g_h3[NB*C0*LSP];
__device__ float g_Lx[NB*C0*LSP];
__device__ float g_s1[NB*C0];
__device__ float g_s2[NB*C0];
__device__ float g_xi[NB*DI*LSP];
__device__ float g_z [NB*DI*LSP];
__device__ float g_xs[NB*DI*LSP];
__device__ float g_delta[NB*DI*LSP];
__device__ float g_Bm[NB*LSP*NS];
__device__ float g_Cm[NB*LSP*NS];
__device__ float g_P [NB*NCH*DI*NS];
__device__ float g_He[NB*NCH*DI*NS];
__device__ float g_y [NB*DI*LSP];

__device__ __forceinline__ float silu(float v) {
    return v / (1.f + __expf(-v));
}

// ---------------- 1) fused upsample + 1x1 conv (144->48) -> h1 ----------------
// grid (LSP/96, NB), block 192; thread tile 4l x 6co
__global__ void __launch_bounds__(192) k_conv1(const float* __restrict__ x,
                                               const float* __restrict__ Hx,
                                               const float* __restrict__ W1,
                                               const float* __restrict__ b1) {
    extern __shared__ float sm[];
    float* sW  = sm;            // 144*48
    float* sIn = sm + 6912;     // 144*96
    int tid = threadIdx.x;
    int b = blockIdx.y;
    int l0 = blockIdx.x * 96;
    if (blockIdx.x == 0 && b == 0 && tid < NB*C0) { g_s1[tid] = 0.f; g_s2[tid] = 0.f; }
    for (int i = tid; i < 144 * 48; i += 192) {
        int ci = i / 48, co = i % 48;
        sW[i] = W1[co * 144 + ci];
    }
    // upsample rows 0..47
    for (int i = tid; i < 48 * 96; i += 192) {
        int ci = i / 96, lq = i % 96;
        int l = l0 + lq;
        int t = l % 24, w = (l / 24) % 24, h = l / 576;
        const float sc = 11.0f / 23.0f;
        float ph = h * sc, pw = w * sc, pt = t * sc;
        int hl = (int)ph, wl = (int)pw, tl = (int)pt;
        float fh = ph - hl, fw = pw - wl, ft = pt - tl;
        int hh = min(hl + 1, 11), wh = min(wl + 1, 11), th = min(tl + 1, 11);
        const float* bp = x + (b * 48 + ci) * 1728;
        float c000 = bp[hl*144 + wl*12 + tl];
        float c001 = bp[hl*144 + wl*12 + th];
        float c010 = bp[hl*144 + wh*12 + tl];
        float c011 = bp[hl*144 + wh*12 + th];
        float c100 = bp[hh*144 + wl*12 + tl];
        float c101 = bp[hh*144 + wl*12 + th];
        float c110 = bp[hh*144 + wh*12 + tl];
        float c111 = bp[hh*144 + wh*12 + th];
        float v00 = c000 + (c001 - c000) * ft;
        float v01 = c010 + (c011 - c010) * ft;
        float v10 = c100 + (c101 - c100) * ft;
        float v11 = c110 + (c111 - c110) * ft;
        float v0 = v00 + (v01 - v00) * fw;
        float v1 = v10 + (v11 - v10) * fw;
        sIn[ci * 96 + lq] = v0 + (v1 - v0) * fh;
    }
    // Hx rows 48..143
    for (int i = tid; i < 96 * 96; i += 192) {
        int ci = i / 96, lq = i % 96;
        sIn[(48 + ci) * 96 + lq] = __ldg(Hx + (b*96 + ci)*LSP + l0 + lq);
    }
    __syncthreads();
    int lg = tid % 24, qg = tid / 24;         // lg: 4 l each; qg: 6 co each
    float acc[24];
#pragma unroll
    for (int i = 0; i < 24; i++) acc[i] = 0.f;
    for (int ci = 0; ci < 144; ci++) {
        float4 a4 = *(const float4*)(sIn + ci*96 + lg*4);
        const float2* wp = (const float2*)(sW + ci*48 + qg*6);
        float2 w0 = wp[0], w1 = wp[1], w2 = wp[2];
        float av[4] = {a4.x, a4.y, a4.z, a4.w};
        float wv[6] = {w0.x, w0.y, w1.x, w1.y, w2.x, w2.y};
#pragma unroll
        for (int li = 0; li < 4; li++)
#pragma unroll
            for (int j = 0; j < 6; j++)
                acc[li*6+j] += av[li] * wv[j];
    }
#pragma unroll
    for (int j = 0; j < 6; j++) {
        int co = qg*6 + j;
        float bv = __ldg(b1 + co);
        float4 o = make_float4(acc[0*6+j]+bv, acc[1*6+j]+bv, acc[2*6+j]+bv, acc[3*6+j]+bv);
        *(float4*)(&g_h1[(b*48 + co)*LSP + l0 + lg*4]) = o;
    }
}

// ---------------- 2) 3x3x3 conv, pad 1, 48->48 : h1 -> h2 ----------------
// tile 4x x 8y x 12z, block (4,8,4)=128, 3 z per thread, 8 co per block
__global__ void __launch_bounds__(128) k_conv2(const float* __restrict__ W2,
                                               const float* __restrict__ b2) {
    __shared__ float sIn[8 * 840];            // 8 ci x (14z x 10y x 6x)  26.9KB
    __shared__ float sW[8 * 27 * 8];          // 6.9KB
    int bz = blockIdx.z;                      // b*6 + cog
    int b = bz / 6, cog = bz % 6;
    int z0 = blockIdx.y * 12;
    int yt = blockIdx.x / 6, xt = blockIdx.x % 6;
    int y0 = yt * 8, x0 = xt * 4;
    int tx = threadIdx.x, ty = threadIdx.y, tz = threadIdx.z;
    int tid = (tz * 8 + ty) * 4 + tx;
    float acc[3][8];
#pragma unroll
    for (int m = 0; m < 3; m++)
#pragma unroll
        for (int i = 0; i < 8; i++) acc[m][i] = 0.f;

    for (int cc = 0; cc < 6; cc++) {
        __syncthreads();
        for (int i = tid; i < 6720; i += 128) {
            int ci = i / 840; int p = i % 840;
            int lz = p / 60; int q2 = p % 60;
            int ly = q2 / 6; int lx = q2 % 6;
            int gz = z0 - 1 + lz, gy = y0 - 1 + ly, gx = x0 - 1 + lx;
            float v = 0.f;
            if (gz >= 0 && gz < 24 && gy >= 0 && gy < 24 && gx >= 0 && gx < 24)
                v = g_h1[(b*48 + cc*8 + ci)*LSP + gz*576 + gy*24 + gx];
            sIn[i] = v;
        }
        for (int i = tid; i < 1728; i += 128) {
            int ci = i / 216; int k = (i / 8) % 27; int co = i % 8;
            sW[i] = W2[((cog*8 + co)*48 + cc*8 + ci)*27 + k];
        }
        __syncthreads();
#pragma unroll 1
        for (int ci = 0; ci < 8; ci++) {
            const float* ip = sIn + ci*840 + (tz*10 + ty)*6 + tx;
            const float* wp = sW + ci*27*8;
#pragma unroll
            for (int kz = 0; kz < 3; kz++)
#pragma unroll
            for (int ky = 0; ky < 3; ky++)
#pragma unroll
            for (int kx = 0; kx < 3; kx++) {
                int off = kz*60 + ky*6 + kx;
                float v0 = ip[off];
                float v1 = ip[off + 240];
                float v2 = ip[off + 480];
                const float4* w4 = (const float4*)(wp + (kz*9 + ky*3 + kx)*8);
                float4 wa = w4[0], wb = w4[1];
                float wv[8] = {wa.x, wa.y, wa.z, wa.w, wb.x, wb.y, wb.z, wb.w};
#pragma unroll
                for (int co = 0; co < 8; co++) {
                    acc[0][co] += wv[co] * v0;
                    acc[1][co] += wv[co] * v1;
                    acc[2][co] += wv[co] * v2;
                }
            }
        }
    }
    int y = y0 + ty, xg = x0 + tx;
#pragma unroll
    for (int co = 0; co < 8; co++) {
        float bv = __ldg(b2 + cog*8 + co);
        int base = (b*48 + cog*8 + co)*LSP + y*24 + xg;
#pragma unroll
        for (int m = 0; m < 3; m++) {
            int z = z0 + tz + 4*m;
            g_h2[base + z*576] = acc[m][co] + bv;
        }
    }
}

// ---------------- 3) 1x1 conv 48->48 + instance-norm partial stats ----------------
// grid (LSP/96, NB), block 192; thread tile 4l x 6co
__global__ void __launch_bounds__(192) k_conv3(const float* __restrict__ W3,
                                               const float* __restrict__ b3) {
    __shared__ float sW[48 * 48];             // 9.2KB
    __shared__ float sIn[48 * 96];            // 18.4KB
    __shared__ float sS1[48], sS2[48];
    int tid = threadIdx.x;
    int b = blockIdx.y;
    int l0 = blockIdx.x * 96;
    if (tid < 48) { sS1[tid] = 0.f; sS2[tid] = 0.f; }
    for (int i = tid; i < 48 * 48; i += 192) {
        int ci = i / 48, co = i % 48;
        sW[i] = W3[co * 48 + ci];
    }
    for (int i = tid; i < 48 * 96; i += 192) {
        int ci = i / 96, lq = i % 96;
        sIn[i] = g_h2[(b*48 + ci)*LSP + l0 + lq];
    }
    __syncthreads();
    int lg = tid % 24, qg = tid / 24;
    float acc[24];
#pragma unroll
    for (int i = 0; i < 24; i++) acc[i] = 0.f;
    for (int ci = 0; ci < 48; ci++) {
        float4 a4 = *(const float4*)(sIn + ci*96 + lg*4);
        const float2* wp = (const float2*)(sW + ci*48 + qg*6);
        float2 w0 = wp[0], w1 = wp[1], w2 = wp[2];
        float av[4] = {a4.x, a4.y, a4.z, a4.w};
        float wv[6] = {w0.x, w0.y, w1.x, w1.y, w2.x, w2.y};
#pragma unroll
        for (int li = 0; li < 4; li++)
#pragma unroll
            for (int j = 0; j < 6; j++)
                acc[li*6+j] += av[li] * wv[j];
    }
#pragma unroll
    for (int j = 0; j < 6; j++) {
        int co = qg*6 + j;
        float bv = __ldg(b3 + co);
        float v0 = acc[0*6+j]+bv, v1 = acc[1*6+j]+bv, v2 = acc[2*6+j]+bv, v3 = acc[3*6+j]+bv;
        *(float4*)(&g_h3[(b*48 + co)*LSP + l0 + lg*4]) = make_float4(v0, v1, v2, v3);
        atomicAdd(&sS1[co], v0 + v1 + v2 + v3);
        atomicAdd(&sS2[co], v0*v0 + v1*v1 + v2*v2 + v3*v3);
    }
    __syncthreads();
    if (tid < 48) {
        atomicAdd(&g_s1[b*48 + tid], sS1[tid]);
        atomicAdd(&g_s2[b*48 + tid], sS2[tid]);
    }
}

// ---------------- 4) norm finalize + SELU + in_proj 48->192 ----------------
// grid (LSP/96, NB), block 384; thread tile 4l x 12e
__global__ void __launch_bounds__(384) k_selu_inproj(const float* __restrict__ Wip) {
    extern __shared__ float sm[];
    float* sW  = sm;            // 48*192
    float* sLx = sm + 9216;     // 48*96
    int tid = threadIdx.x;
    int b = blockIdx.y;
    int l0 = blockIdx.x * 96;
    for (int i = tid; i < 48 * 192; i += 384) {
        int ci = i / 192, e = i % 192;
        sW[i] = Wip[e * 48 + ci];
    }
    const float inv = 1.0f / (float)LSP;
    const float a_ = 1.6732632423543772f, s_ = 1.0507009873554805f;
    for (int i = tid; i < 48 * 96; i += 384) {
        int ci = i / 96, lq = i % 96;
        int bc = b*48 + ci;
        float m = g_s1[bc] * inv;
        float var = g_s2[bc] * inv - m * m;
        float istd = rsqrtf(var + 1e-5f);
        float v = (g_h3[bc*LSP + l0 + lq] - m) * istd;
        float sv = (v > 0.f) ? s_ * v : s_ * a_ * expm1f(v);
        sLx[i] = sv;
        g_Lx[bc*LSP + l0 + lq] = sv;
    }
    __syncthreads();
    int lg = tid % 24, qg = tid / 24;         // qg 0..15, 12 e each
    float acc[48];
#pragma unroll
    for (int i = 0; i < 48; i++) acc[i] = 0.f;
    for (int ci = 0; ci < 48; ci++) {
        float4 a4 = *(const float4*)(sLx + ci*96 + lg*4);
        const float4* wp = (const float4*)(sW + ci*192 + qg*12);
        float4 w0 = wp[0], w1 = wp[1], w2 = wp[2];
        float av[4] = {a4.x, a4.y, a4.z, a4.w};
        float wv[12] = {w0.x,w0.y,w0.z,w0.w, w1.x,w1.y,w1.z,w1.w, w2.x,w2.y,w2.z,w2.w};
#pragma unroll
        for (int li = 0; li < 4; li++)
#pragma unroll
            for (int j = 0; j < 12; j++)
                acc[li*12+j] += av[li] * wv[j];
    }
#pragma unroll
    for (int j = 0; j < 12; j++) {
        int e = qg*12 + j;
        float4 o = make_float4(acc[0*12+j], acc[1*12+j], acc[2*12+j], acc[3*12+j]);
        if (e < 96) *(float4*)(&g_xi[(b*96 + e)*LSP + l0 + lg*4]) = o;
        else        *(float4*)(&g_z [(b*96 + (e-96))*LSP + l0 + lg*4]) = o;
    }
}

// ---------------- 5) fused conv1d+SiLU -> xs, x_proj, dt_proj+softplus ----------------
// grid (LSP/128, NB), block 256
__global__ void __launch_bounds__(256) k_xproj(const float* __restrict__ cw,
                                               const float* __restrict__ cb,
                                               const float* __restrict__ xw,
                                               const float* __restrict__ dtw,
                                               const float* __restrict__ dtb) {
    extern __shared__ float sm[];
    float* sxs = sm;            // 96*128
    float* sWx = sm + 12288;    // 40*96
    float* sdt = sm + 16128;    // 128*3
    int tid = threadIdx.x;
    int b = blockIdx.y;
    int l0 = blockIdx.x * 128;
    for (int i = tid; i < 40 * 96; i += 256)
        sWx[i] = (i < 35 * 96) ? xw[i] : 0.f;
    for (int i = tid; i < 96 * 128; i += 256) {
        int d = i >> 7, lq = i & 127;
        int l = l0 + lq;
        const float* xp = g_xi + (b*96 + d)*LSP;
        float s = __ldg(cb + d);
#pragma unroll
        for (int k = 0; k < 4; k++) {
            int li = l - 3 + k;
            if (li >= 0) s += __ldg(cw + d*4 + k) * __ldg(xp + li);
        }
        float xv = silu(s);
        sxs[i] = xv;
        g_xs[(b*96 + d)*LSP + l] = xv;
    }
    __syncthreads();
    int lg = tid & 31, qg = tid >> 5;         // qg 0..7, 5 e each
    float acc[20];
#pragma unroll
    for (int i = 0; i < 20; i++) acc[i] = 0.f;
    for (int ci = 0; ci < 96; ci++) {
        float4 a4 = *(const float4*)(sxs + ci*128 + lg*4);
        float av[4] = {a4.x, a4.y, a4.z, a4.w};
        float wv[5];
#pragma unroll
        for (int j = 0; j < 5; j++) wv[j] = sWx[(qg*5 + j)*96 + ci];
#pragma unroll
        for (int li = 0; li < 4; li++)
#pragma unroll
            for (int j = 0; j < 5; j++)
                acc[li*5+j] += av[li] * wv[j];
    }
#pragma unroll
    for (int j = 0; j < 5; j++) {
        int e = qg*5 + j;
#pragma unroll
        for (int li = 0; li < 4; li++) {
            int lq = lg*4 + li;
            float val = acc[li*5+j];
            if (e < 3)       sdt[lq*3 + e] = val;
            else if (e < 19) g_Bm[(b*LSP + l0 + lq)*16 + (e - 3)]  = val;
            else if (e < 35) g_Cm[(b*LSP + l0 + lq)*16 + (e - 19)] = val;
        }
    }
    __syncthreads();
    for (int i = tid; i < 96 * 128; i += 256) {
        int d = i >> 7, lq2 = i & 127;
        float t = __ldg(dtb + d) + __ldg(dtw + d*3)     * sdt[lq2*3]
                                 + __ldg(dtw + d*3 + 1) * sdt[lq2*3 + 1]
                                 + __ldg(dtw + d*3 + 2) * sdt[lq2*3 + 2];
        float dl = (t > 20.f) ? t : log1pf(__expf(t));
        g_delta[(b*96 + d)*LSP + l0 + lq2] = dl;
    }
}

// ---------------- 6) scan phase A ----------------
__global__ void __launch_bounds__(512) k_scanA(const float* __restrict__ Alog) {
    int b = blockIdx.z, dg = blockIdx.y, ch = blockIdx.x;
    int dl_ = threadIdx.x >> 4, n = threadIdx.x & 15;
    int d = dg * 32 + dl_;
    float A = -__expf(__ldg(Alog + d*16 + n));
    const float* dp = g_delta + (b*96 + d)*LSP + ch*CS;
    const float* xp = g_xs    + (b*96 + d)*LSP + ch*CS;
    const float* Bp = g_Bm + (b*LSP + ch*CS)*16 + n;
    float h = 0.f, P = 1.f;
#pragma unroll 4
    for (int i = 0; i < CS; i++) {
        float dv = __ldg(dp + i);
        float a = __expf(dv * A);
        h = a * h + (dv * __ldg(xp + i)) * __ldg(Bp + i*16);
        P *= a;
    }
    int si = ((b*NCH + ch)*DI + d)*NS + n;
    g_P[si] = P; g_He[si] = h;
}

// ---------------- 7) scan phase C: inline carry + replay, emit y ----------------
__global__ void __launch_bounds__(512) k_scanC(const float* __restrict__ Alog) {
    int b = blockIdx.z, dg = blockIdx.y, ch = blockIdx.x;
    int dl_ = threadIdx.x >> 4, n = threadIdx.x & 15;
    int d = dg * 32 + dl_;
    float A = -__expf(__ldg(Alog + d*16 + n));
    float h = 0.f;
    for (int k = 0; k < ch; k++) {
        int si = ((b*NCH + k)*DI + d)*NS + n;
        h = g_P[si] * h + g_He[si];
    }
    const float* dp = g_delta + (b*96 + d)*LSP + ch*CS;
    const float* xp = g_xs    + (b*96 + d)*LSP + ch*CS;
    const float* Bp = g_Bm + (b*LSP + ch*CS)*16 + n;
    const float* Cp = g_Cm + (b*LSP + ch*CS)*16 + n;
    float* yp = g_y + (b*96 + d)*LSP + ch*CS;
    float yreg = 0.f;
#pragma unroll 4
    for (int i = 0; i < CS; i++) {
        float dv = __ldg(dp + i);
        float a = __expf(dv * A);
        h = a * h + (dv * __ldg(xp + i)) * __ldg(Bp + i*16);
        float p = h * __ldg(Cp + i*16);
        p += __shfl_xor_sync(0xffffffffu, p, 8, 16);
        p += __shfl_xor_sync(0xffffffffu, p, 4, 16);
        p += __shfl_xor_sync(0xffffffffu, p, 2, 16);
        p += __shfl_xor_sync(0xffffffffu, p, 1, 16);
        if ((i & 15) == n) yreg = p;
        if ((i & 15) == 15) yp[(i & ~15) + n] = yreg;
    }
}

// ---------------- 8) epilogue: (y + D*xs)*silu(z) -> out_proj -> + Lx ----------------
// grid (LSP/128, NB), block 256; thread tile 4l x 6e
__global__ void __launch_bounds__(256) k_epi(const float* __restrict__ Wo,
                                             const float* __restrict__ Dp,
                                             float* __restrict__ outp) {
    extern __shared__ float sm[];
    float* sy2 = sm;            // 96*128
    float* sW  = sm + 12288;    // 96*48
    int tid = threadIdx.x;
    int b = blockIdx.y;
    int l0 = blockIdx.x * 128;
    for (int i = tid; i < 96 * 48; i += 256) {
        int d = i / 48, e = i % 48;
        sW[i] = Wo[e*96 + d];
    }
    for (int i = tid; i < 96 * 128; i += 256) {
        int d = i >> 7, lq = i & 127;
        int o = (b*96 + d)*LSP + l0 + lq;
        float yv = __ldg(g_y + o), xv = __ldg(g_xs + o), zv = __ldg(g_z + o);
        sy2[i] = (yv + __ldg(Dp + d) * xv) * silu(zv);
    }
    __syncthreads();
    int lg = tid & 31, qg = tid >> 5;         // qg 0..7, 6 e each
    float acc[24];
#pragma unroll
    for (int i = 0; i < 24; i++) acc[i] = 0.f;
    for (int d = 0; d < 96; d++) {
        float4 a4 = *(const float4*)(sy2 + d*128 + lg*4);
        const float2* wp = (const float2*)(sW + d*48 + qg*6);
        float2 w0 = wp[0], w1 = wp[1], w2 = wp[2];
        float av[4] = {a4.x, a4.y, a4.z, a4.w};
        float wv[6] = {w0.x, w0.y, w1.x, w1.y, w2.x, w2.y};
#pragma unroll
        for (int li = 0; li < 4; li++)
#pragma unroll
            for (int j = 0; j < 6; j++)
                acc[li*6+j] += av[li] * wv[j];
    }
#pragma unroll
    for (int j = 0; j < 6; j++) {
        int e = qg*6 + j;
        int o = (b*48 + e)*LSP + l0 + lg*4;
        float4 r = *(const float4*)(&g_Lx[o]);
        *(float4*)(&outp[o]) = make_float4(acc[0*6+j]+r.x, acc[1*6+j]+r.y,
                                           acc[2*6+j]+r.z, acc[3*6+j]+r.w);
    }
}

// ---------------- launcher ----------------
extern "C" void kernel_launch(void* const* d_in, const int* in_sizes, int n_in,
                              void* d_out, int out_size) {
    const float* x    = (const float*)d_in[0];
    const float* Hx   = (const float*)d_in[1];
    const float* W1   = (const float*)d_in[2];
    const float* b1   = (const float*)d_in[3];
    const float* W2   = (const float*)d_in[4];
    const float* b2   = (const float*)d_in[5];
    const float* W3   = (const float*)d_in[6];
    const float* b3   = (const float*)d_in[7];
    const float* Wip  = (const float*)d_in[8];
    const float* cw   = (const float*)d_in[9];
    const float* cb   = (const float*)d_in[10];
    const float* xw   = (const float*)d_in[11];
    const float* dtw  = (const float*)d_in[12];
    const float* dtb  = (const float*)d_in[13];
    const float* Alog = (const float*)d_in[14];
    const float* Dp   = (const float*)d_in[15];
    const float* Wo   = (const float*)d_in[16];
    float* outp = (float*)d_out;

    const int smem_conv1 = (144*48 + 144*96) * 4;          // 82944
    const int smem_selu  = (48*192 + 48*96) * 4;           // 55296
    const int smem_xproj = (96*128 + 40*96 + 128*3) * 4;   // 66048
    const int smem_epi   = (96*128 + 96*48) * 4;           // 67584
    cudaFuncSetAttribute(k_conv1,       cudaFuncAttributeMaxDynamicSharedMemorySize, smem_conv1);
    cudaFuncSetAttribute(k_selu_inproj, cudaFuncAttributeMaxDynamicSharedMemorySize, smem_selu);
    cudaFuncSetAttribute(k_xproj,       cudaFuncAttributeMaxDynamicSharedMemorySize, smem_xproj);
    cudaFuncSetAttribute(k_epi,         cudaFuncAttributeMaxDynamicSharedMemorySize, smem_epi);

    k_conv1<<<dim3(LSP/96, NB), 192, smem_conv1>>>(x, Hx, W1, b1);
    dim3 g2(18, 2, 12), t2(4, 8, 4);
    k_conv2<<<g2, t2>>>(W2, b2);
    k_conv3<<<dim3(LSP/96, NB), 192>>>(W3, b3);
    k_selu_inproj<<<dim3(LSP/96, NB), 384, smem_selu>>>(Wip);
    k_xproj<<<dim3(LSP/128, NB), 256, smem_xproj>>>(cw, cb, xw, dtw, dtb);
    dim3 gs(NCH, 3, NB);
    k_scanA<<<gs, 512>>>(Alog);
    k_scanC<<<gs, 512>>>(Alog);
    k_epi<<<dim3(LSP/128, NB), 256, smem_epi>>>(Wo, Dp, outp);
}